// round 9
// baseline (speedup 1.0000x reference)
#include <cuda_runtime.h>

#define P 49152
#define J 16
#define DL 10
#define H 64
#define OUTN (3 * P)            // 147456 output elements
#define W2_JSTRIDE (3 * P * H)  // floats per j-slice of w2 = 9437184
#define RPW 8                   // row-pairs per warp (16 outputs per warp)

// dh[j][h] = relu(w1·feat + b1) - relu(w1·zfeat + b1), 16x64 floats
__device__ float g_dh[J * H];

// ---------------------------------------------------------------------------
// Kernel 1: compute dh. One block of 1024 threads, thread = (j, h).
// ---------------------------------------------------------------------------
__global__ void dh_kernel(const float* __restrict__ x,
                          const float* __restrict__ latent,
                          const float* __restrict__ w1,
                          const float* __restrict__ b1,
                          const int*   __restrict__ nidx,
                          const float* __restrict__ nmask) {
    __shared__ float sfeat[J * 27];   // masked neighbor pose features
    __shared__ float slat[J * DL];    // latent codes

    int tid = threadIdx.x;
    if (tid < J * 27) {
        int j = tid / 27;
        int i = tid % 27;
        int k = i / 9;
        int t = i % 9;
        int src = nidx[j * 3 + k];
        sfeat[tid] = x[src * 9 + t] * nmask[j * 3 + k];
    }
    if (tid < J * DL) {
        slat[tid] = latent[tid];
    }
    __syncthreads();

    int j = tid >> 6;   // /64
    const float* wrow = w1 + (size_t)tid * (27 + DL);

    float s0 = b1[tid];
    #pragma unroll
    for (int d = 0; d < DL; ++d)
        s0 = fmaf(wrow[27 + d], slat[j * DL + d], s0);

    float s1 = s0;
    #pragma unroll
    for (int i = 0; i < 27; ++i)
        s1 = fmaf(wrow[i], sfeat[j * 27 + i], s1);

    g_dh[tid] = fmaxf(s1, 0.f) - fmaxf(s0, 0.f);
}

// ---------------------------------------------------------------------------
// Kernel 2 (coalesced): 16 lanes cooperate per output row of w2.
//   lane l in [0,16) owns float4 column-chunk l of the 256B row.
//   A warp covers 2 adjacent rows -> every LDG.128 reads 512 contiguous bytes.
//   Each warp processes RPW row-pairs = 2*RPW outputs; grid doubled vs R6 to
//   lift occupancy from the grid-limited 45% toward the 75% register limit.
// out[o] = iv[o] + 1e-3 * sum_j relu(mask[j,o/3]) * <dh[j,:], w2[j,o,:]>
// ---------------------------------------------------------------------------
__global__ void __launch_bounds__(256) laplacian_main_kernel(
        const float* __restrict__ iv,
        const float* __restrict__ mask,
        const float* __restrict__ w2,
        float* __restrict__ out) {
    __shared__ float4 sdh[J * H / 4];   // 1024 floats = 4 KB

    int tid = threadIdx.x;
    sdh[tid] = ((const float4*)g_dh)[tid];   // 256 threads x float4 = 4 KB
    __syncthreads();

    int warp = tid >> 5;
    int lane = tid & 31;
    int l    = lane & 15;      // column-chunk within the row
    int grp  = lane >> 4;      // 0 or 1: which row of the pair
    int obase = (blockIdx.x * 8 + warp) * (2 * RPW);  // 1152 blocks * 8 * 16 = 147456

    #pragma unroll 1
    for (int rp = 0; rp < RPW; ++rp) {
        int og = obase + 2 * rp + grp;   // this group's output index
        int p  = og / 3;
        const float4* wrow =
            reinterpret_cast<const float4*>(w2) + (size_t)og * (H / 4) + l;

        // j fully unrolled: 16 independent coalesced LDG.128s in flight
        float a0 = 0.f, a1 = 0.f;
        #pragma unroll
        for (int j = 0; j < J; ++j) {
            float  s  = fmaxf(__ldg(&mask[j * P + p]), 0.f);   // broadcast in group
            float4 wv = __ldg(wrow + (size_t)j * (W2_JSTRIDE / 4));
            float4 dv = sdh[j * 16 + l];                       // conflict-free LDS
            float d;
            d = wv.x * dv.x;
            d = fmaf(wv.y, dv.y, d);
            d = fmaf(wv.z, dv.z, d);
            d = fmaf(wv.w, dv.w, d);
            if (j & 1) a1 = fmaf(s, d, a1);
            else       a0 = fmaf(s, d, a0);
        }
        float acc = a0 + a1;

        // reduce across the 16 lanes of the group (xor 8,4,2,1 stays in-group)
        acc += __shfl_xor_sync(0xffffffffu, acc, 8);
        acc += __shfl_xor_sync(0xffffffffu, acc, 4);
        acc += __shfl_xor_sync(0xffffffffu, acc, 2);
        acc += __shfl_xor_sync(0xffffffffu, acc, 1);

        if (l == 0)   // lanes 0 and 16: one writer per output
            out[og] = iv[og] + acc * 1e-3f;
    }
}

// ---------------------------------------------------------------------------
// Launch. Inputs (metadata order):
//  0 x (144)  1 input_verts (147456)  2 latent_code (160)  3 mask_param (786432)
//  4 w1 (37888)  5 b1 (1024)  6 w2 (150994944)  7 b2 (unused)  8 neighbor_idxs (48 i32)
//  9 neighbor_mask (48)
// ---------------------------------------------------------------------------
extern "C" void kernel_launch(void* const* d_in, const int* in_sizes, int n_in,
                              void* d_out, int out_size) {
    const float* x      = (const float*)d_in[0];
    const float* iv     = (const float*)d_in[1];
    const float* latent = (const float*)d_in[2];
    const float* maskp  = (const float*)d_in[3];
    const float* w1     = (const float*)d_in[4];
    const float* b1     = (const float*)d_in[5];
    const float* w2     = (const float*)d_in[6];
    const int*   nidx   = (const int*)d_in[8];
    const float* nmask  = (const float*)d_in[9];
    float* out = (float*)d_out;

    dh_kernel<<<1, 1024>>>(x, latent, w1, b1, nidx, nmask);
    laplacian_main_kernel<<<OUTN / (8 * 2 * RPW), 256>>>(iv, maskp, w2, out);
}

// round 13
// speedup vs baseline: 1.1047x; 1.1047x over previous
#include <cuda_runtime.h>

#define P 49152
#define J 16
#define DL 10
#define H 64
#define OUTN (3 * P)            // 147456 output elements
#define W2_JSTRIDE (3 * P * H)  // floats per j-slice of w2 = 9437184
#define TRP 8                   // row-pairs per tile
#define NTILES 2                // tiles per warp -> 32 outputs per warp

// dh[j][h] = relu(w1·feat + b1) - relu(w1·zfeat + b1), 16x64 floats
__device__ float g_dh[J * H];

// ---------------------------------------------------------------------------
// Kernel 1: compute dh. One block of 1024 threads, thread = (j, h).
// ---------------------------------------------------------------------------
__global__ void dh_kernel(const float* __restrict__ x,
                          const float* __restrict__ latent,
                          const float* __restrict__ w1,
                          const float* __restrict__ b1,
                          const int*   __restrict__ nidx,
                          const float* __restrict__ nmask) {
    __shared__ float sfeat[J * 27];   // masked neighbor pose features
    __shared__ float slat[J * DL];    // latent codes

    int tid = threadIdx.x;
    if (tid < J * 27) {
        int j = tid / 27;
        int i = tid % 27;
        int k = i / 9;
        int t = i % 9;
        int src = nidx[j * 3 + k];
        sfeat[tid] = x[src * 9 + t] * nmask[j * 3 + k];
    }
    if (tid < J * DL) {
        slat[tid] = latent[tid];
    }
    __syncthreads();

    int j = tid >> 6;   // /64
    const float* wrow = w1 + (size_t)tid * (27 + DL);

    float s0 = b1[tid];
    #pragma unroll
    for (int d = 0; d < DL; ++d)
        s0 = fmaf(wrow[27 + d], slat[j * DL + d], s0);

    float s1 = s0;
    #pragma unroll
    for (int i = 0; i < 27; ++i)
        s1 = fmaf(wrow[i], sfeat[j * 27 + i], s1);

    g_dh[tid] = fmaxf(s1, 0.f) - fmaxf(s0, 0.f);
}

// ---------------------------------------------------------------------------
// Kernel 2: j-outer / row-inner for DRAM streaming locality.
//   16 lanes cooperate per w2 row (lane l owns float4 chunk l).
//   Per j, a warp issues TRP consecutive LDG.128s covering 4 KB of
//   CONTIGUOUS w2 (rp-offsets are compile-time immediates off one base),
//   instead of 16 streams 36 MB apart. dv (dh chunk) loaded once per j.
// out[o] = iv[o] + 1e-3 * sum_j relu(mask[j,o/3]) * <dh[j,:], w2[j,o,:]>
// ---------------------------------------------------------------------------
__global__ void __launch_bounds__(256) laplacian_main_kernel(
        const float* __restrict__ iv,
        const float* __restrict__ mask,
        const float* __restrict__ w2,
        float* __restrict__ out) {
    __shared__ float4 sdh[J * H / 4];   // 1024 floats = 4 KB

    int tid = threadIdx.x;
    sdh[tid] = ((const float4*)g_dh)[tid];   // 256 threads x float4 = 4 KB
    __syncthreads();

    int warp = tid >> 5;
    int lane = tid & 31;
    int l    = lane & 15;      // column-chunk within the row
    int grp  = lane >> 4;      // 0 or 1: which row of the pair
    int obase = (blockIdx.x * 8 + warp) * (NTILES * 2 * TRP);  // 576 blocks

    #pragma unroll 1
    for (int tile = 0; tile < NTILES; ++tile) {
        int ob = obase + tile * (2 * TRP) + grp;  // group's first output in tile
        const float4* base =
            reinterpret_cast<const float4*>(w2) + (size_t)ob * (H / 4) + l;

        float acc[TRP];
        #pragma unroll
        for (int rp = 0; rp < TRP; ++rp) acc[rp] = 0.f;

        #pragma unroll 1
        for (int j = 0; j < J; ++j) {
            float4 dv = sdh[j * 16 + l];               // one LDS per j
            const float4* wj = base + (size_t)j * (W2_JSTRIDE / 4);
            #pragma unroll
            for (int rp = 0; rp < TRP; ++rp) {
                // rp offset = rp * 2 rows * 16 float4 = immediate (512 B apart)
                float4 wv = __ldg(wj + rp * 32);
                float  s  = fmaxf(__ldg(&mask[j * P + (ob + 2 * rp) / 3]), 0.f);
                float d;
                d = wv.x * dv.x;
                d = fmaf(wv.y, dv.y, d);
                d = fmaf(wv.z, dv.z, d);
                d = fmaf(wv.w, dv.w, d);
                acc[rp] = fmaf(s, d, acc[rp]);
            }
        }

        // reduce each accumulator across the 16 lanes of the group
        #pragma unroll
        for (int rp = 0; rp < TRP; ++rp) {
            float a = acc[rp];
            a += __shfl_xor_sync(0xffffffffu, a, 8);
            a += __shfl_xor_sync(0xffffffffu, a, 4);
            a += __shfl_xor_sync(0xffffffffu, a, 2);
            a += __shfl_xor_sync(0xffffffffu, a, 1);
            if (l == 0) {
                int og = ob + 2 * rp;
                out[og] = iv[og] + a * 1e-3f;
            }
        }
    }
}

// ---------------------------------------------------------------------------
// Launch. Inputs (metadata order):
//  0 x (144)  1 input_verts (147456)  2 latent_code (160)  3 mask_param (786432)
//  4 w1 (37888)  5 b1 (1024)  6 w2 (150994944)  7 b2 (unused)  8 neighbor_idxs (48 i32)
//  9 neighbor_mask (48)
// ---------------------------------------------------------------------------
extern "C" void kernel_launch(void* const* d_in, const int* in_sizes, int n_in,
                              void* d_out, int out_size) {
    const float* x      = (const float*)d_in[0];
    const float* iv     = (const float*)d_in[1];
    const float* latent = (const float*)d_in[2];
    const float* maskp  = (const float*)d_in[3];
    const float* w1     = (const float*)d_in[4];
    const float* b1     = (const float*)d_in[5];
    const float* w2     = (const float*)d_in[6];
    const int*   nidx   = (const int*)d_in[8];
    const float* nmask  = (const float*)d_in[9];
    float* out = (float*)d_out;

    dh_kernel<<<1, 1024>>>(x, latent, w1, b1, nidx, nmask);
    laplacian_main_kernel<<<OUTN / (8 * NTILES * 2 * TRP), 256>>>(iv, maskp, w2, out);
}